// round 2
// baseline (speedup 1.0000x reference)
#include <cuda_runtime.h>
#include <cstdint>

#define B_SZ 2048
#define K_SZ 64
#define D_SZ 768      // C*E*E
#define F_SZ 64       // CF_FEAT
#define KT   16       // K-tile of the score GEMM

// ---------------- device scratch (no allocations allowed) ----------------
__device__ float g_WpT[D_SZ * F_SZ];    // Wphi  transposed: [d][f]
__device__ float g_WtT[D_SZ * F_SZ];    // Wtheta transposed: [d][f]
__device__ float g_scores[B_SZ * K_SZ]; // scores[b][k]

// ---------------- K0: transpose Wtheta / Wphi for coalesced reads --------
__global__ void k_transpose(const float* __restrict__ Wth,
                            const float* __restrict__ Wph) {
    int i = blockIdx.x * blockDim.x + threadIdx.x;
    if (i < D_SZ * F_SZ) {
        int d = i / F_SZ, f = i % F_SZ;
        g_WtT[i] = Wth[f * D_SZ + d];
        g_WpT[i] = Wph[f * D_SZ + d];
    }
}

// ---------------- K2: fused x_feat + p_feat GEMM + norm + scores ---------
// Each CTA handles 2 batch rows (128 (b,k) GEMM rows x 64 features, K=768).
// f32x2 packed FMA accumulators: thread micro-tile = 4 rows x 8 features.
__global__ __launch_bounds__(256) void k_scores(
    const float* __restrict__ p_im, const float* __restrict__ x_im,
    const float* __restrict__ btheta, const float* __restrict__ bphi)
{
    __shared__ float As[2][128][20];   // p_im tile [row][kk], pad->20
    __shared__ float Bs[2][KT][64];    // WphiT tile [kk][f]
    __shared__ float xs[2][D_SZ];      // x_im rows for the 2 b's
    __shared__ float Xf[2][F_SZ];      // normalized x_feat
    __shared__ float bps[F_SZ];        // bphi
    __shared__ float xnorm[2];

    const int tid = threadIdx.x;
    const int b0  = blockIdx.x * 2;
    const float* Abase = p_im + (size_t)b0 * K_SZ * D_SZ; // 128 contiguous rows

    // ---- prologue: load x_im rows + bphi ----
    for (int i = tid; i < 2 * D_SZ; i += 256) {
        int r = i / D_SZ, d = i % D_SZ;
        xs[r][d] = x_im[(size_t)(b0 + r) * D_SZ + d];
    }
    if (tid < F_SZ) bps[tid] = bphi[tid];
    __syncthreads();

    // ---- x_feat = l2norm(Wtheta @ x_im + btheta), fp32, per-CTA ----
    if (tid < 128) {
        int r = tid >> 6, f = tid & 63;
        float a0 = 0.f, a1 = 0.f, a2 = 0.f, a3 = 0.f;
        #pragma unroll 4
        for (int d = 0; d < D_SZ; d += 4) {
            a0 = fmaf(g_WtT[(d + 0) * F_SZ + f], xs[r][d + 0], a0);
            a1 = fmaf(g_WtT[(d + 1) * F_SZ + f], xs[r][d + 1], a1);
            a2 = fmaf(g_WtT[(d + 2) * F_SZ + f], xs[r][d + 2], a2);
            a3 = fmaf(g_WtT[(d + 3) * F_SZ + f], xs[r][d + 3], a3);
        }
        Xf[r][f] = btheta[f] + ((a0 + a1) + (a2 + a3));
    }
    __syncthreads();
    if (tid < 2) {
        float n2 = 0.f;
        for (int f = 0; f < F_SZ; f++) { float v = Xf[tid][f]; n2 += v * v; }
        xnorm[tid] = 1.0f / fmaxf(sqrtf(n2), 1e-12f);
    }
    __syncthreads();
    if (tid < 128) {
        int r = tid >> 6, f = tid & 63;
        Xf[r][f] *= xnorm[r];
    }
    // (visibility of Xf guaranteed by the main-loop __syncthreads)

    // ---- main GEMM: feat[row][f] = Wphi @ p_im[row] ----
    const int tr = tid >> 3;   // 0..31 -> rows tr*4 .. tr*4+3
    const int tc = tid & 7;    // 0..7  -> features tc*8 .. tc*8+7
    unsigned long long acc[4][4];
    #pragma unroll
    for (int i = 0; i < 4; i++)
        #pragma unroll
        for (int j = 0; j < 4; j++) acc[i][j] = 0ULL;

    // load tile 0
    {
        #pragma unroll
        for (int i = 0; i < 2; i++) {
            int idx4 = tid + 256 * i;
            int row = idx4 >> 2, c4 = idx4 & 3;
            float4 v = *(const float4*)(Abase + row * D_SZ + 0 + c4 * 4);
            *(float4*)&As[0][row][c4 * 4] = v;
        }
        int kk = tid >> 4, fg = tid & 15;
        float4 v = *(const float4*)(g_WpT + (0 + kk) * F_SZ + fg * 4);
        *(float4*)&Bs[0][kk][fg * 4] = v;
    }
    __syncthreads();

    int buf = 0;
    #pragma unroll 1
    for (int t = 0; t < D_SZ / KT; t++) {
        float4 pa0, pa1, pb;
        const bool has = (t + 1 < D_SZ / KT);
        if (has) {
            const int ktn = (t + 1) * KT;
            int idx4 = tid; int row = idx4 >> 2, c4 = idx4 & 3;
            pa0 = *(const float4*)(Abase + row * D_SZ + ktn + c4 * 4);
            idx4 = tid + 256; row = idx4 >> 2; c4 = idx4 & 3;
            pa1 = *(const float4*)(Abase + row * D_SZ + ktn + c4 * 4);
            int kk = tid >> 4, fg = tid & 15;
            pb = *(const float4*)(g_WpT + (ktn + kk) * F_SZ + fg * 4);
        }
        #pragma unroll
        for (int kk = 0; kk < KT; kk++) {
            unsigned long long bp[4];
            #pragma unroll
            for (int j = 0; j < 4; j++)
                bp[j] = *(const unsigned long long*)&Bs[buf][kk][tc * 8 + j * 2];
            #pragma unroll
            for (int i = 0; i < 4; i++) {
                float a = As[buf][tr * 4 + i][kk];
                unsigned long long ap;
                asm("mov.b64 %0, {%1, %1};" : "=l"(ap) : "r"(__float_as_uint(a)));
                #pragma unroll
                for (int j = 0; j < 4; j++)
                    asm("fma.rn.f32x2 %0, %1, %2, %0;"
                        : "+l"(acc[i][j]) : "l"(ap), "l"(bp[j]));
            }
        }
        if (has) {
            const int nb = buf ^ 1;
            int idx4 = tid; int row = idx4 >> 2, c4 = idx4 & 3;
            *(float4*)&As[nb][row][c4 * 4] = pa0;
            idx4 = tid + 256; row = idx4 >> 2; c4 = idx4 & 3;
            *(float4*)&As[nb][row][c4 * 4] = pa1;
            int kk = tid >> 4, fg = tid & 15;
            *(float4*)&Bs[nb][kk][fg * 4] = pb;
        }
        __syncthreads();
        buf ^= 1;
    }

    // ---- epilogue: +bphi, norm over f, dot with x_feat, scores ----
    const int f0 = tc * 8;
    #pragma unroll
    for (int i = 0; i < 4; i++) {
        const int row = tr * 4 + i;
        const int r = row >> 6;  // which of the 2 b's
        float n2 = 0.f, dp = 0.f;
        #pragma unroll
        for (int j = 0; j < 4; j++) {
            unsigned lo, hi;
            asm("mov.b64 {%0, %1}, %2;" : "=r"(lo), "=r"(hi) : "l"(acc[i][j]));
            float v0 = __uint_as_float(lo) + bps[f0 + 2 * j];
            float v1 = __uint_as_float(hi) + bps[f0 + 2 * j + 1];
            n2 = fmaf(v0, v0, n2); n2 = fmaf(v1, v1, n2);
            dp = fmaf(Xf[r][f0 + 2 * j], v0, dp);
            dp = fmaf(Xf[r][f0 + 2 * j + 1], v1, dp);
        }
        #pragma unroll
        for (int o = 4; o; o >>= 1) {
            n2 += __shfl_xor_sync(0xffffffffu, n2, o);
            dp += __shfl_xor_sync(0xffffffffu, dp, o);
        }
        if (tc == 0)
            g_scores[b0 * K_SZ + row] = dp / fmaxf(sqrtf(n2), 1e-12f);
    }
}

// ---------------- K4: softmax + switch + sparse weighted sum + mix -------
__global__ __launch_bounds__(256) void k_output(
    const float* __restrict__ x, const float* __restrict__ p,
    const float* __restrict__ Wg, const float* __restrict__ bg,
    const float* __restrict__ Wo, const float* __restrict__ bo,
    const float* __restrict__ sig_scale, const float* __restrict__ sig_shift,
    float* __restrict__ out)
{
    __shared__ float ws[K_SZ];
    __shared__ float s_m, s_inv, s_sw;
    const int b = blockIdx.x, tid = threadIdx.x;

    if (tid < K_SZ) ws[tid] = g_scores[b * K_SZ + tid];
    __syncthreads();
    if (tid == 0) {
        float m = -1e30f;
        for (int k = 0; k < K_SZ; k++) m = fmaxf(m, ws[k]);
        s_m = m;
        float z = m * sig_scale[0] + sig_shift[0];
        s_sw = 1.0f / (1.0f + expf(-z));
    }
    __syncthreads();
    if (tid < K_SZ) ws[tid] = expf(1048576.0f * (ws[tid] - s_m)); // sharpness
    __syncthreads();
    if (tid == 0) {
        float s = 0.f;
        for (int k = 0; k < K_SZ; k++) s += ws[k];
        s_inv = 1.0f / s;
    }
    __syncthreads();

    const float inv = s_inv;
    const float sw  = s_sw;

    // Sparse weighted sum over k: only slices with non-negligible weight.
    // thread t owns hw=t for all 3 channels (d = c*256 + t).
    float acc0 = 0.f, acc1 = 0.f, acc2 = 0.f;
    const float* pb = p + (size_t)b * K_SZ * D_SZ;
    for (int k = 0; k < K_SZ; k++) {
        float wk = ws[k] * inv;
        if (wk > 1e-12f) {                  // uniform branch (smem broadcast)
            const float* pr = pb + k * D_SZ;
            acc0 = fmaf(wk, pr[tid],       acc0);
            acc1 = fmaf(wk, pr[tid + 256], acc1);
            acc2 = fmaf(wk, pr[tid + 512], acc2);
        }
    }

    // channel mix: mixed = Wg*acc + bg ; pa = Wo*mixed + bo
    float mx0 = fmaf(Wg[0], acc0, fmaf(Wg[1], acc1, fmaf(Wg[2], acc2, bg[0])));
    float mx1 = fmaf(Wg[3], acc0, fmaf(Wg[4], acc1, fmaf(Wg[5], acc2, bg[1])));
    float mx2 = fmaf(Wg[6], acc0, fmaf(Wg[7], acc1, fmaf(Wg[8], acc2, bg[2])));

    const float* xb = x + (size_t)b * D_SZ;
    float* ob = out + (size_t)b * D_SZ;
    #pragma unroll
    for (int o = 0; o < 3; o++) {
        float pa = fmaf(Wo[o * 3 + 0], mx0,
                   fmaf(Wo[o * 3 + 1], mx1,
                   fmaf(Wo[o * 3 + 2], mx2, bo[o])));
        float xv = xb[o * 256 + tid];
        ob[o * 256 + tid] = xv * (1.0f - sw) + pa * sw;
    }
}

// ---------------- launch ----------------
extern "C" void kernel_launch(void* const* d_in, const int* in_sizes, int n_in,
                              void* d_out, int out_size) {
    const float* x         = (const float*)d_in[0];
    const float* p         = (const float*)d_in[1];
    const float* x_im      = (const float*)d_in[2];
    const float* p_im      = (const float*)d_in[3];
    const float* Wtheta    = (const float*)d_in[4];
    const float* btheta    = (const float*)d_in[5];
    const float* Wphi      = (const float*)d_in[6];
    const float* bphi      = (const float*)d_in[7];
    const float* Wg        = (const float*)d_in[8];
    const float* bg        = (const float*)d_in[9];
    const float* Wo        = (const float*)d_in[10];
    const float* bo        = (const float*)d_in[11];
    const float* sig_scale = (const float*)d_in[12];
    const float* sig_shift = (const float*)d_in[13];
    float* out = (float*)d_out;

    k_transpose<<<(D_SZ * F_SZ + 255) / 256, 256>>>(Wtheta, Wphi);
    k_scores<<<B_SZ / 2, 256>>>(p_im, x_im, btheta, bphi);
    k_output<<<B_SZ, 256>>>(x, p, Wg, bg, Wo, bo, sig_scale, sig_shift, out);
}

// round 6
// speedup vs baseline: 3.5767x; 3.5767x over previous
#include <cuda_runtime.h>
#include <cuda_bf16.h>
#include <cstdint>

#define B_SZ 2048
#define K_SZ 64
#define D_SZ 768      // C*E*E
#define F_SZ 64       // CF_FEAT
#define KC   64       // k elements per chunk
#define NCHUNK (D_SZ / KC)   // 12
#define ROWS 128      // GEMM rows per CTA
#define LDT  72       // padded smem row length (elements)

// smem byte offsets
#define OFF_AHI   0
#define OFF_ALO   18432            // 128*144
#define OFF_BHI   36864
#define OFF_BLO   46080            // +64*144
#define OFF_XF    55296
#define OFF_BIAS  55808
#define SMEM_BYTES 56064

// ---------------- device scratch ----------------
__device__ float g_scores[B_SZ * K_SZ];
__device__ float g_Xf[B_SZ * F_SZ];
__device__ __align__(16) __nv_bfloat16 g_BphHi[F_SZ * D_SZ];
__device__ __align__(16) __nv_bfloat16 g_BphLo[F_SZ * D_SZ];
__device__ __align__(16) __nv_bfloat16 g_BthHi[F_SZ * D_SZ];
__device__ __align__(16) __nv_bfloat16 g_BthLo[F_SZ * D_SZ];

// ---------------- helpers ----------------
__device__ __forceinline__ uint32_t smem_u32(const void* p) {
    uint32_t a;
    asm("{ .reg .u64 t; cvta.to.shared.u64 t, %1; cvt.u32.u64 %0, t; }"
        : "=r"(a) : "l"(p));
    return a;
}
#define LDSM4(r, addr) \
    asm volatile("ldmatrix.sync.aligned.m8n8.x4.shared.b16 {%0,%1,%2,%3}, [%4];" \
        : "=r"((r)[0]), "=r"((r)[1]), "=r"((r)[2]), "=r"((r)[3]) : "r"(addr))
#define MMA16816(c, a, b0, b1) \
    asm volatile("mma.sync.aligned.m16n8k16.row.col.f32.bf16.bf16.f32 " \
        "{%0,%1,%2,%3}, {%4,%5,%6,%7}, {%8,%9}, {%0,%1,%2,%3};" \
        : "+f"((c)[0]), "+f"((c)[1]), "+f"((c)[2]), "+f"((c)[3]) \
        : "r"((a)[0]), "r"((a)[1]), "r"((a)[2]), "r"((a)[3]), "r"(b0), "r"(b1))

__device__ __forceinline__ uint32_t pack_hi(float x, float y,
                                            float& lx, float& ly) {
    __nv_bfloat16 hx = __float2bfloat16(x), hy = __float2bfloat16(y);
    lx = x - __bfloat162float(hx);
    ly = y - __bfloat162float(hy);
    return ((uint32_t)__bfloat16_as_ushort(hy) << 16) | __bfloat16_as_ushort(hx);
}
__device__ __forceinline__ uint32_t pack_bf(float x, float y) {
    return ((uint32_t)__bfloat16_as_ushort(__float2bfloat16(y)) << 16)
         | __bfloat16_as_ushort(__float2bfloat16(x));
}

// ---------------- K0: split W's into bf16 hi/lo ----------------
__global__ void k_prep(const float* __restrict__ Wth, const float* __restrict__ Wph) {
    int i = blockIdx.x * 256 + threadIdx.x;
    if (i < F_SZ * D_SZ) {
        float a = Wph[i];
        __nv_bfloat16 h = __float2bfloat16(a);
        g_BphHi[i] = h;
        g_BphLo[i] = __float2bfloat16(a - __bfloat162float(h));
        float b = Wth[i];
        __nv_bfloat16 g = __float2bfloat16(b);
        g_BthHi[i] = g;
        g_BthLo[i] = __float2bfloat16(b - __bfloat162float(g));
    }
}

// ---------------- K1/K2: HMMA feature GEMM + fused epilogue ----------------
// mode 1: src = x_im (16 CTAs)   -> writes normalized g_Xf
// mode 0: src = p_im (1024 CTAs) -> writes g_scores (norm + dot with x_feat)
__global__ __launch_bounds__(256) void k_feat(const float* __restrict__ src,
                                              const float* __restrict__ bias,
                                              int mode) {
    extern __shared__ __align__(16) char sp[];
    const uint32_t sb = smem_u32(sp);
    const int tid = threadIdx.x;
    const int w = tid >> 5, lane = tid & 31;

    const __nv_bfloat16* gBhi = mode ? g_BthHi : g_BphHi;
    const __nv_bfloat16* gBlo = mode ? g_BthLo : g_BphLo;

    if (tid < F_SZ) ((float*)(sp + OFF_BIAS))[tid] = bias[tid];
    if (mode == 0 && tid < 128)
        ((float*)(sp + OFF_XF))[tid] = g_Xf[(size_t)blockIdx.x * 128 + tid];

    const float* Ab = src + (size_t)blockIdx.x * ROWS * D_SZ;

    float4 ar[8];
    uint2 bh[4], bl[4];
#define LOAD_A(t) do {                                                          \
    _Pragma("unroll")                                                           \
    for (int i = 0; i < 8; i++) {                                               \
        int l = tid + 256 * i; int row = l >> 4, c4 = l & 15;                   \
        ar[i] = *(const float4*)(Ab + row * D_SZ + (t) * KC + c4 * 4);          \
    } } while (0)
#define LOAD_B(t) do {                                                          \
    _Pragma("unroll")                                                           \
    for (int i = 0; i < 4; i++) {                                               \
        int l = tid + 256 * i; int row = l >> 4, u = l & 15;                    \
        bh[i] = *(const uint2*)(gBhi + row * D_SZ + (t) * KC + u * 4);          \
        bl[i] = *(const uint2*)(gBlo + row * D_SZ + (t) * KC + u * 4);          \
    } } while (0)

    LOAD_A(0); LOAD_B(0);

    float acc[8][4];
#pragma unroll
    for (int j = 0; j < 8; j++)
#pragma unroll
        for (int q = 0; q < 4; q++) acc[j][q] = 0.f;

    // ldmatrix address components
    const int m8  = lane & 7;
    const int grp = lane >> 3;
    const uint32_t aoffBase = (uint32_t)((16 * w + (grp & 1) * 8 + m8) * 144
                                         + ((grp >> 1) * 8) * 2);
    const uint32_t brow     = (uint32_t)(((grp >> 1) * 8 + m8) * 144);
    const uint32_t bcolg    = (uint32_t)(((grp & 1) * 8) * 2);

#pragma unroll 1
    for (int t = 0; t < NCHUNK; t++) {
        // ---- store A chunk (hi/lo split), 2-way STS conflicts at worst ----
#pragma unroll
        for (int i = 0; i < 8; i++) {
            int l = tid + 256 * i; int row = l >> 4, c4 = l & 15;
            float4 v = ar[i];
            float l0, l1, l2, l3;
            uint32_t h01 = pack_hi(v.x, v.y, l0, l1);
            uint32_t h23 = pack_hi(v.z, v.w, l2, l3);
            uint32_t q01 = pack_bf(l0, l1);
            uint32_t q23 = pack_bf(l2, l3);
            uint32_t off = (uint32_t)(row * 144 + c4 * 8);
            *(uint2*)(sp + OFF_AHI + off) = make_uint2(h01, h23);
            *(uint2*)(sp + OFF_ALO + off) = make_uint2(q01, q23);
        }
#pragma unroll
        for (int i = 0; i < 4; i++) {
            int l = tid + 256 * i; int row = l >> 4, u = l & 15;
            uint32_t off = (uint32_t)(row * 144 + u * 8);
            *(uint2*)(sp + OFF_BHI + off) = bh[i];
            *(uint2*)(sp + OFF_BLO + off) = bl[i];
        }
        __syncthreads();

        if (t + 1 < NCHUNK) { LOAD_A(t + 1); LOAD_B(t + 1); }  // hide LDG

        // ---- consume: 4 k-steps x (2 A-ldsm + 8 B-ldsm + 24 mma) ----
#pragma unroll
        for (int ks = 0; ks < 4; ks++) {
            uint32_t ah[4], al[4];
            uint32_t aoff = aoffBase + (uint32_t)(ks * 32);
            LDSM4(ah, sb + OFF_AHI + aoff);
            LDSM4(al, sb + OFF_ALO + aoff);
#pragma unroll
            for (int tp = 0; tp < 4; tp++) {
                uint32_t bhr[4], blr[4];
                uint32_t boff = (uint32_t)(tp * 16 * 144) + brow
                              + bcolg + (uint32_t)(ks * 32);
                LDSM4(bhr, sb + OFF_BHI + boff);
                LDSM4(blr, sb + OFF_BLO + boff);
                MMA16816(acc[2 * tp],     ah, bhr[0], bhr[1]);
                MMA16816(acc[2 * tp + 1], ah, bhr[2], bhr[3]);
                MMA16816(acc[2 * tp],     ah, blr[0], blr[1]);
                MMA16816(acc[2 * tp + 1], ah, blr[2], blr[3]);
                MMA16816(acc[2 * tp],     al, bhr[0], bhr[1]);
                MMA16816(acc[2 * tp + 1], al, bhr[2], bhr[3]);
            }
        }
        __syncthreads();
    }

    // ---- epilogue: +bias, l2-norm, (dot with x_feat) ----
    const int qr = lane >> 2, qc = lane & 3;
    const float* bs = (const float*)(sp + OFF_BIAS);
#pragma unroll
    for (int h = 0; h < 2; h++) {
        const int row = 16 * w + h * 8 + qr;
        float n2 = 0.f, dp = 0.f;
        const float* xf = (const float*)(sp + OFF_XF) + (row >> 6) * 64;
#pragma unroll
        for (int j = 0; j < 8; j++) {
            int c = j * 8 + qc * 2;
            float v0 = acc[j][h * 2 + 0] + bs[c];
            float v1 = acc[j][h * 2 + 1] + bs[c + 1];
            n2 = fmaf(v0, v0, n2); n2 = fmaf(v1, v1, n2);
            if (mode == 0) {
                dp = fmaf(xf[c], v0, dp);
                dp = fmaf(xf[c + 1], v1, dp);
            }
        }
        n2 += __shfl_xor_sync(0xffffffffu, n2, 1);
        n2 += __shfl_xor_sync(0xffffffffu, n2, 2);
        if (mode == 0) {
            dp += __shfl_xor_sync(0xffffffffu, dp, 1);
            dp += __shfl_xor_sync(0xffffffffu, dp, 2);
            if (qc == 0)
                g_scores[(size_t)blockIdx.x * 128 + row] =
                    dp / fmaxf(sqrtf(n2), 1e-12f);
        } else {
            float inv = 1.0f / fmaxf(sqrtf(n2), 1e-12f);
            float* o = g_Xf + ((size_t)blockIdx.x * 128 + row) * 64;
#pragma unroll
            for (int j = 0; j < 8; j++) {
                int c = j * 8 + qc * 2;
                o[c]     = (acc[j][h * 2 + 0] + bs[c]) * inv;
                o[c + 1] = (acc[j][h * 2 + 1] + bs[c + 1]) * inv;
            }
        }
    }
}

// ---------------- K3: softmax + switch + sparse weighted sum + mix -------
__global__ __launch_bounds__(256) void k_output(
    const float* __restrict__ x, const float* __restrict__ p,
    const float* __restrict__ Wg, const float* __restrict__ bg,
    const float* __restrict__ Wo, const float* __restrict__ bo,
    const float* __restrict__ sig_scale, const float* __restrict__ sig_shift,
    float* __restrict__ out)
{
    __shared__ float ws[K_SZ];
    __shared__ float s_m, s_inv, s_sw;
    const int b = blockIdx.x, tid = threadIdx.x;

    if (tid < K_SZ) ws[tid] = g_scores[b * K_SZ + tid];
    __syncthreads();
    if (tid == 0) {
        float m = -1e30f;
        for (int k = 0; k < K_SZ; k++) m = fmaxf(m, ws[k]);
        s_m = m;
        float z = m * sig_scale[0] + sig_shift[0];
        s_sw = 1.0f / (1.0f + expf(-z));
    }
    __syncthreads();
    if (tid < K_SZ) ws[tid] = expf(1048576.0f * (ws[tid] - s_m)); // sharpness
    __syncthreads();
    if (tid == 0) {
        float s = 0.f;
        for (int k = 0; k < K_SZ; k++) s += ws[k];
        s_inv = 1.0f / s;
    }
    __syncthreads();

    const float inv = s_inv;
    const float sw  = s_sw;

    float acc0 = 0.f, acc1 = 0.f, acc2 = 0.f;
    const float* pb = p + (size_t)b * K_SZ * D_SZ;
    for (int k = 0; k < K_SZ; k++) {
        float wk = ws[k] * inv;
        if (wk > 1e-12f) {
            const float* pr = pb + k * D_SZ;
            acc0 = fmaf(wk, pr[tid],       acc0);
            acc1 = fmaf(wk, pr[tid + 256], acc1);
            acc2 = fmaf(wk, pr[tid + 512], acc2);
        }
    }

    float mx0 = fmaf(Wg[0], acc0, fmaf(Wg[1], acc1, fmaf(Wg[2], acc2, bg[0])));
    float mx1 = fmaf(Wg[3], acc0, fmaf(Wg[4], acc1, fmaf(Wg[5], acc2, bg[1])));
    float mx2 = fmaf(Wg[6], acc0, fmaf(Wg[7], acc1, fmaf(Wg[8], acc2, bg[2])));

    const float* xb = x + (size_t)b * D_SZ;
    float* ob = out + (size_t)b * D_SZ;
#pragma unroll
    for (int o = 0; o < 3; o++) {
        float pa = fmaf(Wo[o * 3 + 0], mx0,
                   fmaf(Wo[o * 3 + 1], mx1,
                   fmaf(Wo[o * 3 + 2], mx2, bo[o])));
        float xv = xb[o * 256 + tid];
        ob[o * 256 + tid] = xv * (1.0f - sw) + pa * sw;
    }
}

// ---------------- launch ----------------
extern "C" void kernel_launch(void* const* d_in, const int* in_sizes, int n_in,
                              void* d_out, int out_size) {
    const float* x         = (const float*)d_in[0];
    const float* p         = (const float*)d_in[1];
    const float* x_im      = (const float*)d_in[2];
    const float* p_im      = (const float*)d_in[3];
    const float* Wtheta    = (const float*)d_in[4];
    const float* btheta    = (const float*)d_in[5];
    const float* Wphi      = (const float*)d_in[6];
    const float* bphi      = (const float*)d_in[7];
    const float* Wg        = (const float*)d_in[8];
    const float* bg        = (const float*)d_in[9];
    const float* Wo        = (const float*)d_in[10];
    const float* bo        = (const float*)d_in[11];
    const float* sig_scale = (const float*)d_in[12];
    const float* sig_shift = (const float*)d_in[13];
    float* out = (float*)d_out;

    static int s_attr_done = 0;
    if (!s_attr_done) {
        cudaFuncSetAttribute(k_feat, cudaFuncAttributeMaxDynamicSharedMemorySize,
                             SMEM_BYTES);
        s_attr_done = 1;
    }

    k_prep<<<(F_SZ * D_SZ + 255) / 256, 256>>>(Wtheta, Wphi);
    k_feat<<<B_SZ / 128, 256, SMEM_BYTES>>>(x_im, btheta, 1);           // x_feat
    k_feat<<<B_SZ * K_SZ / 128, 256, SMEM_BYTES>>>(p_im, bphi, 0);      // scores
    k_output<<<B_SZ, 256>>>(x, p, Wg, bg, Wo, bo, sig_scale, sig_shift, out);
}